// round 11
// baseline (speedup 1.0000x reference)
#include <cuda_runtime.h>

// CplxGaussianRBF: out[b,c,p,{re,im}] = sum_w exp(-|x[b,c,p]-mu[w]|^2/(2*sd[w])) * w_{re,im}[c,w] + bias
// B=4, C=32, H=W=64 (HW=4096), NW=64.
//
// R10: R8's poly offload regressed -> MUFU is NOT the binder; issue<=60% with no
// saturated pipe across R5-R8 says latency-bound / grid-capped occupancy
// (1024 blocks = 6.9/SM). Revert to R7 math (weight-pair f32x2 packing, 1 ex2 per
// pixel-weight on MUFU, 3 broadcast LDS.128 per weight-pair) and quadruple the
// block count: 128-thread blocks, grid 2048, so occupancy is no longer grid-capped
// (~2x eligible warps per SMSP to hide LDS29/MUFU16 chains).

#define CN   32
#define HWN  4096
#define NWN  64

typedef unsigned long long u64t;

__device__ __forceinline__ u64t fma2(u64t a, u64t b, u64t c) {
    u64t d;
    asm("fma.rn.f32x2 %0, %1, %2, %3;" : "=l"(d) : "l"(a), "l"(b), "l"(c));
    return d;
}
__device__ __forceinline__ u64t pack2(float lo, float hi) {
    u64t d;
    asm("mov.b64 %0, {%1, %2};" : "=l"(d) : "f"(lo), "f"(hi));
    return d;
}
__device__ __forceinline__ void unpack2(u64t v, float& lo, float& hi) {
    asm("mov.b64 {%0, %1}, %2;" : "=f"(lo), "=f"(hi) : "l"(v));
}
__device__ __forceinline__ u64t ex2_2(u64t v) {
    float t0, t1;
    unpack2(v, t0, t1);
    float e0, e1;
    asm("ex2.approx.f32 %0, %1;" : "=f"(e0) : "f"(t0));
    asm("ex2.approx.f32 %0, %1;" : "=f"(e1) : "f"(t1));
    return pack2(e0, e1);
}

__global__ __launch_bounds__(128)
void cplx_rbf_kernel(
    const float* __restrict__ xr, const float* __restrict__ xi,
    const float* __restrict__ wr, const float* __restrict__ wi,
    const float* __restrict__ br, const float* __restrict__ bi,
    const float* __restrict__ mur, const float* __restrict__ mui,
    const float* __restrict__ sd,
    float* __restrict__ out)
{
    // Per weight-pair j (weights 2j, 2j+1):
    //   s_ab[j] = {A0, A1, B0, B1}; s_cd[j] = {C0, C1, D0, D1}; s_wp[j] = {wr0, wr1, wi0, wi1}
    __shared__ __align__(16) float s_ab[NWN * 2];
    __shared__ __align__(16) float s_cd[NWN * 2];
    __shared__ __align__(16) float s_wp[NWN * 2];

    const int t  = threadIdx.x;
    const int bc = blockIdx.x >> 4;           // (b*C + c) slice index (16 blocks/slice)
    const int c  = bc & (CN - 1);

    if (t < NWN / 2) {
        const int w0 = 2 * t, w1 = 2 * t + 1;
        const float cf0 = -0.7213475204444817f / sd[w0];   // -log2(e)/(2*sd)
        const float cf1 = -0.7213475204444817f / sd[w1];
        const float mr0 = mur[w0], mi0 = mui[w0];
        const float mr1 = mur[w1], mi1 = mui[w1];
        reinterpret_cast<float4*>(s_ab)[t] =
            make_float4(cf0, cf1, -2.0f * cf0 * mr0, -2.0f * cf1 * mr1);
        reinterpret_cast<float4*>(s_cd)[t] =
            make_float4(-2.0f * cf0 * mi0, -2.0f * cf1 * mi1,
                        cf0 * fmaf(mr0, mr0, mi0 * mi0),
                        cf1 * fmaf(mr1, mr1, mi1 * mi1));
        reinterpret_cast<float4*>(s_wp)[t] =
            make_float4(wr[c * NWN + w0], wr[c * NWN + w1],
                        wi[c * NWN + w0], wi[c * NWN + w1]);
    }
    __syncthreads();

    const int p0   = ((blockIdx.x & 15) << 8) + (t << 1);   // 2 pixels per thread
    const int base = bc * HWN;

    const float2 x_r = *reinterpret_cast<const float2*>(xr + base + p0);
    const float2 x_i = *reinterpret_cast<const float2*>(xi + base + p0);

    // duplicated per-pixel packed values
    const u64t xr0d = pack2(x_r.x, x_r.x);
    const u64t xi0d = pack2(x_i.x, x_i.x);
    const u64t xr1d = pack2(x_r.y, x_r.y);
    const u64t xi1d = pack2(x_i.y, x_i.y);
    const float n0 = fmaf(x_r.x, x_r.x, x_i.x * x_i.x);
    const float n1 = fmaf(x_r.y, x_r.y, x_i.y * x_i.y);
    const u64t n0d = pack2(n0, n0);
    const u64t n1d = pack2(n1, n1);

    u64t accr0 = 0ULL, acci0 = 0ULL;   // {sum even w, sum odd w}
    u64t accr1 = 0ULL, acci1 = 0ULL;

    const ulonglong2* ab2 = reinterpret_cast<const ulonglong2*>(s_ab);
    const ulonglong2* cd2 = reinterpret_cast<const ulonglong2*>(s_cd);
    const ulonglong2* wp2 = reinterpret_cast<const ulonglong2*>(s_wp);

#pragma unroll
    for (int j = 0; j < NWN / 2; j++) {
        const ulonglong2 ab = ab2[j];   // .x = {A0,A1},   .y = {B0,B1}
        const ulonglong2 cd = cd2[j];   // .x = {C0,C1},   .y = {D0,D1}
        const ulonglong2 wp = wp2[j];   // .x = {wr0,wr1}, .y = {wi0,wi1}

        u64t e0 = fma2(ab.x, n0d, cd.y);   // A*n + D
        u64t e1 = fma2(ab.x, n1d, cd.y);
        e0 = fma2(ab.y, xr0d, e0);         // + B*xr
        e1 = fma2(ab.y, xr1d, e1);
        e0 = fma2(cd.x, xi0d, e0);         // + C*xi
        e1 = fma2(cd.x, xi1d, e1);

        const u64t g0 = ex2_2(e0);
        const u64t g1 = ex2_2(e1);

        accr0 = fma2(g0, wp.x, accr0);
        acci0 = fma2(g0, wp.y, acci0);
        accr1 = fma2(g1, wp.x, accr1);
        acci1 = fma2(g1, wp.y, acci1);
    }

    float a, b2;
    const float brc = br[c];
    const float bic = bi[c];

    float4 o;
    unpack2(accr0, a, b2);  o.x = a + b2 + brc;   // pixel p0   real
    unpack2(acci0, a, b2);  o.y = a + b2 + bic;   // pixel p0   imag
    unpack2(accr1, a, b2);  o.z = a + b2 + brc;   // pixel p0+1 real
    unpack2(acci1, a, b2);  o.w = a + b2 + bic;   // pixel p0+1 imag
    *reinterpret_cast<float4*>(out + (size_t)(base + p0) * 2) = o;
}

extern "C" void kernel_launch(void* const* d_in, const int* in_sizes, int n_in,
                              void* d_out, int out_size)
{
    const float* xr  = (const float*)d_in[0];  // x_real  (4,32,64,64)
    const float* xi  = (const float*)d_in[1];  // x_imag
    const float* wr  = (const float*)d_in[2];  // w_real  (32,64)
    const float* wi  = (const float*)d_in[3];  // w_imag
    const float* br  = (const float*)d_in[4];  // b_real  (1,32,1)
    const float* bi  = (const float*)d_in[5];  // b_imag
    const float* mur = (const float*)d_in[6];  // mu_real (64)
    const float* mui = (const float*)d_in[7];  // mu_imag (64)
    const float* sd  = (const float*)d_in[8];  // stddev  (64)
    float* out = (float*)d_out;                // (4,32,64,64,2)

    // 4*32*4096 pixels / (128 threads * 2 pixels) = 2048 blocks
    cplx_rbf_kernel<<<2048, 128>>>(xr, xi, wr, wi, br, bi, mur, mui, sd, out);
}

// round 14
// speedup vs baseline: 1.3814x; 1.3814x over previous
#include <cuda_runtime.h>

// CplxGaussianRBF: out[b,c,p,{re,im}] = sum_w exp(-|x[b,c,p]-mu[w]|^2/(2*sd[w])) * w_{re,im}[c,w] + bias
// B=4, C=32, H=W=64 (HW=4096), NW=64.
//
// R12: R11's theta=0.25 MUFU/fma exp split was right, but its deg-3 poly
// coefficients were wrong (rel_err 1.9e-3). Swap in R8's VALIDATED deg-4 minimax
// set (measured 9.8e-6 at theta=0.5). Everything else identical to R11:
// 1024x256 blocks, weight-pair f32x2 packing, odd-j pixel-1 exp on the fma pipe.
// Balance: MUFU 10.6k cyc vs fma ~12.4k cyc per SMSP -> ~12.4us.

#define CN   32
#define HWN  4096
#define NWN  64

typedef unsigned long long u64t;

__device__ __forceinline__ u64t fma2(u64t a, u64t b, u64t c) {
    u64t d;
    asm("fma.rn.f32x2 %0, %1, %2, %3;" : "=l"(d) : "l"(a), "l"(b), "l"(c));
    return d;
}
__device__ __forceinline__ u64t add2(u64t a, u64t b) {
    u64t d;
    asm("add.rn.f32x2 %0, %1, %2;" : "=l"(d) : "l"(a), "l"(b));
    return d;
}
__device__ __forceinline__ u64t mul2(u64t a, u64t b) {
    u64t d;
    asm("mul.rn.f32x2 %0, %1, %2;" : "=l"(d) : "l"(a), "l"(b));
    return d;
}
__device__ __forceinline__ u64t pack2(float lo, float hi) {
    u64t d;
    asm("mov.b64 %0, {%1, %2};" : "=l"(d) : "f"(lo), "f"(hi));
    return d;
}
__device__ __forceinline__ void unpack2(u64t v, float& lo, float& hi) {
    asm("mov.b64 {%0, %1}, %2;" : "=f"(lo), "=f"(hi) : "l"(v));
}
__device__ __forceinline__ u64t pack2u(unsigned lo, unsigned hi) {
    u64t d;
    asm("mov.b64 %0, {%1, %2};" : "=l"(d) : "r"(lo), "r"(hi));
    return d;
}
__device__ __forceinline__ void unpack2u(u64t v, unsigned& lo, unsigned& hi) {
    asm("mov.b64 {%0, %1}, %2;" : "=r"(lo), "=r"(hi) : "l"(v));
}
__device__ __forceinline__ u64t ex2_2(u64t v) {
    float t0, t1;
    unpack2(v, t0, t1);
    float e0, e1;
    asm("ex2.approx.f32 %0, %1;" : "=f"(e0) : "f"(t0));
    asm("ex2.approx.f32 %0, %1;" : "=f"(e1) : "f"(t1));
    return pack2(e0, e1);
}

// Packed software exp2 for t <= 0 (underflow-safe: scale clamps at 2^-124; the
// clamped path multiplies a bounded poly by ~2^-124 -> ~0). Deg-4 minimax set
// validated in R8 (rel_err 9.8e-6 at theta=0.5).
#define EXP2_MAGIC   0x4B400000u
#define EXP2_CLAMP   (EXP2_MAGIC - 124u)
#define EXP2_K       (127u - EXP2_MAGIC)

struct Exp2Consts {
    u64t magic2, negmagic2, negone2, c4, c3, c2, c1, c0;
};

__device__ __forceinline__ u64t exp2_poly2(u64t t, const Exp2Consts& k) {
    u64t r = add2(t, k.magic2);                 // round-to-nearest int (biased bits)
    unsigned rl, rh;
    unpack2u(r, rl, rh);
    rl = (rl < EXP2_CLAMP) ? EXP2_CLAMP : rl;   // IMNMX.U32 (alu pipe)
    rh = (rh < EXP2_CLAMP) ? EXP2_CLAMP : rh;
    u64t rc  = pack2u(rl, rh);
    u64t i_f = add2(rc, k.negmagic2);           // i as float pair
    u64t f   = fma2(i_f, k.negone2, t);         // f = t - i, in [-0.5, 0.5]
    u64t p   = fma2(f, k.c4, k.c3);             // deg-4 minimax for 2^f
    p        = fma2(f, p, k.c2);
    p        = fma2(f, p, k.c1);
    p        = fma2(f, p, k.c0);
    unsigned sl = (rl + EXP2_K) << 23;          // 2^i bits (alu pipe)
    unsigned sh = (rh + EXP2_K) << 23;
    return mul2(p, pack2u(sl, sh));             // 2^i * 2^f
}

__global__ __launch_bounds__(256)
void cplx_rbf_kernel(
    const float* __restrict__ xr, const float* __restrict__ xi,
    const float* __restrict__ wr, const float* __restrict__ wi,
    const float* __restrict__ br, const float* __restrict__ bi,
    const float* __restrict__ mur, const float* __restrict__ mui,
    const float* __restrict__ sd,
    float* __restrict__ out)
{
    // Per weight-pair j (weights 2j, 2j+1):
    //   s_ab[j] = {A0, A1, B0, B1}; s_cd[j] = {C0, C1, D0, D1}; s_wp[j] = {wr0, wr1, wi0, wi1}
    __shared__ __align__(16) float s_ab[NWN * 2];
    __shared__ __align__(16) float s_cd[NWN * 2];
    __shared__ __align__(16) float s_wp[NWN * 2];

    const int t  = threadIdx.x;
    const int bc = blockIdx.x >> 3;           // (b*C + c) slice index (8 blocks/slice)
    const int c  = bc & (CN - 1);

    if (t < NWN / 2) {
        const int w0 = 2 * t, w1 = 2 * t + 1;
        const float cf0 = -0.7213475204444817f / sd[w0];   // -log2(e)/(2*sd)
        const float cf1 = -0.7213475204444817f / sd[w1];
        const float mr0 = mur[w0], mi0 = mui[w0];
        const float mr1 = mur[w1], mi1 = mui[w1];
        reinterpret_cast<float4*>(s_ab)[t] =
            make_float4(cf0, cf1, -2.0f * cf0 * mr0, -2.0f * cf1 * mr1);
        reinterpret_cast<float4*>(s_cd)[t] =
            make_float4(-2.0f * cf0 * mi0, -2.0f * cf1 * mi1,
                        cf0 * fmaf(mr0, mr0, mi0 * mi0),
                        cf1 * fmaf(mr1, mr1, mi1 * mi1));
        reinterpret_cast<float4*>(s_wp)[t] =
            make_float4(wr[c * NWN + w0], wr[c * NWN + w1],
                        wi[c * NWN + w0], wi[c * NWN + w1]);
    }
    __syncthreads();

    Exp2Consts k;
    k.magic2    = pack2(12582912.0f, 12582912.0f);
    k.negmagic2 = pack2(-12582912.0f, -12582912.0f);
    k.negone2   = pack2(-1.0f, -1.0f);
    k.c4        = pack2(0.0096183607f, 0.0096183607f);   // R8-validated deg-4 set
    k.c3        = pack2(0.0555033329f, 0.0555033329f);
    k.c2        = pack2(0.2402264476f, 0.2402264476f);
    k.c1        = pack2(0.6931470590f, 0.6931470590f);
    k.c0        = pack2(1.0000000000f, 1.0000000000f);

    const int p0   = ((blockIdx.x & 7) << 9) + (t << 1);   // 2 pixels per thread
    const int base = bc * HWN;

    const float2 x_r = *reinterpret_cast<const float2*>(xr + base + p0);
    const float2 x_i = *reinterpret_cast<const float2*>(xi + base + p0);

    // duplicated per-pixel packed values
    const u64t xr0d = pack2(x_r.x, x_r.x);
    const u64t xi0d = pack2(x_i.x, x_i.x);
    const u64t xr1d = pack2(x_r.y, x_r.y);
    const u64t xi1d = pack2(x_i.y, x_i.y);
    const float n0 = fmaf(x_r.x, x_r.x, x_i.x * x_i.x);
    const float n1 = fmaf(x_r.y, x_r.y, x_i.y * x_i.y);
    const u64t n0d = pack2(n0, n0);
    const u64t n1d = pack2(n1, n1);

    u64t accr0 = 0ULL, acci0 = 0ULL;   // {sum even w, sum odd w}
    u64t accr1 = 0ULL, acci1 = 0ULL;

    const ulonglong2* ab2 = reinterpret_cast<const ulonglong2*>(s_ab);
    const ulonglong2* cd2 = reinterpret_cast<const ulonglong2*>(s_cd);
    const ulonglong2* wp2 = reinterpret_cast<const ulonglong2*>(s_wp);

#pragma unroll
    for (int j = 0; j < NWN / 2; j++) {
        const ulonglong2 ab = ab2[j];   // .x = {A0,A1},   .y = {B0,B1}
        const ulonglong2 cd = cd2[j];   // .x = {C0,C1},   .y = {D0,D1}
        const ulonglong2 wp = wp2[j];   // .x = {wr0,wr1}, .y = {wi0,wi1}

        u64t e0 = fma2(ab.x, n0d, cd.y);   // A*n + D
        u64t e1 = fma2(ab.x, n1d, cd.y);
        e0 = fma2(ab.y, xr0d, e0);         // + B*xr
        e1 = fma2(ab.y, xr1d, e1);
        e0 = fma2(cd.x, xi0d, e0);         // + C*xi
        e1 = fma2(cd.x, xi1d, e1);

        const u64t g0 = ex2_2(e0);                              // MUFU always
        const u64t g1 = (j & 1) ? exp2_poly2(e1, k)             // odd j: fma-pipe poly
                                : ex2_2(e1);                    // even j: MUFU
        // theta = 0.25 of all exp scalars on the fma pipe

        accr0 = fma2(g0, wp.x, accr0);
        acci0 = fma2(g0, wp.y, acci0);
        accr1 = fma2(g1, wp.x, accr1);
        acci1 = fma2(g1, wp.y, acci1);
    }

    float a, b2;
    const float brc = br[c];
    const float bic = bi[c];

    float4 o;
    unpack2(accr0, a, b2);  o.x = a + b2 + brc;   // pixel p0   real
    unpack2(acci0, a, b2);  o.y = a + b2 + bic;   // pixel p0   imag
    unpack2(accr1, a, b2);  o.z = a + b2 + brc;   // pixel p0+1 real
    unpack2(acci1, a, b2);  o.w = a + b2 + bic;   // pixel p0+1 imag
    *reinterpret_cast<float4*>(out + (size_t)(base + p0) * 2) = o;
}

extern "C" void kernel_launch(void* const* d_in, const int* in_sizes, int n_in,
                              void* d_out, int out_size)
{
    const float* xr  = (const float*)d_in[0];  // x_real  (4,32,64,64)
    const float* xi  = (const float*)d_in[1];  // x_imag
    const float* wr  = (const float*)d_in[2];  // w_real  (32,64)
    const float* wi  = (const float*)d_in[3];  // w_imag
    const float* br  = (const float*)d_in[4];  // b_real  (1,32,1)
    const float* bi  = (const float*)d_in[5];  // b_imag
    const float* mur = (const float*)d_in[6];  // mu_real (64)
    const float* mui = (const float*)d_in[7];  // mu_imag (64)
    const float* sd  = (const float*)d_in[8];  // stddev  (64)
    float* out = (float*)d_out;                // (4,32,64,64,2)

    // 4*32*4096 pixels / (256 threads * 2 pixels) = 1024 blocks
    cplx_rbf_kernel<<<1024, 256>>>(xr, xi, wr, wi, br, bi, mur, mui, sd, out);
}

// round 15
// speedup vs baseline: 1.5424x; 1.1165x over previous
#include <cuda_runtime.h>

// CplxGaussianRBF: out[b,c,p,{re,im}] = sum_w exp(-|x[b,c,p]-mu[w]|^2/(2*sd[w])) * w_{re,im}[c,w] + bias
// B=4, C=32, H=W=64 (HW=4096), NW=64.
//
// R15: exp-offload family falsified (dur monotonic in instruction count:
// theta=0/.25/.5 -> 14.6/15.9/17.3us). Back to R7 exactly (pure ex2 on MUFU,
// weight-pair f32x2 packing, 1024x256), plus ONE change: explicit depth-2
// software pipeline on the coefficient LDS.128s — prefetch iteration j+1's
// {ab, cd, wp} while computing iteration j, lifting the 29-cycle LDS latency
// off the per-iteration critical path (issue was stuck at 60% on scoreboard
// stalls). Zero added instructions; +6 u64 regs (occ unaffected: achieved ~34
// warps << 51-warp reg cap).

#define CN   32
#define HWN  4096
#define NWN  64

typedef unsigned long long u64t;

__device__ __forceinline__ u64t fma2(u64t a, u64t b, u64t c) {
    u64t d;
    asm("fma.rn.f32x2 %0, %1, %2, %3;" : "=l"(d) : "l"(a), "l"(b), "l"(c));
    return d;
}
__device__ __forceinline__ u64t pack2(float lo, float hi) {
    u64t d;
    asm("mov.b64 %0, {%1, %2};" : "=l"(d) : "f"(lo), "f"(hi));
    return d;
}
__device__ __forceinline__ void unpack2(u64t v, float& lo, float& hi) {
    asm("mov.b64 {%0, %1}, %2;" : "=f"(lo), "=f"(hi) : "l"(v));
}
__device__ __forceinline__ u64t ex2_2(u64t v) {
    float t0, t1;
    unpack2(v, t0, t1);
    float e0, e1;
    asm("ex2.approx.f32 %0, %1;" : "=f"(e0) : "f"(t0));
    asm("ex2.approx.f32 %0, %1;" : "=f"(e1) : "f"(t1));
    return pack2(e0, e1);
}

__global__ __launch_bounds__(256)
void cplx_rbf_kernel(
    const float* __restrict__ xr, const float* __restrict__ xi,
    const float* __restrict__ wr, const float* __restrict__ wi,
    const float* __restrict__ br, const float* __restrict__ bi,
    const float* __restrict__ mur, const float* __restrict__ mui,
    const float* __restrict__ sd,
    float* __restrict__ out)
{
    // Per weight-pair j (weights 2j, 2j+1):
    //   s_ab[j] = {A0, A1, B0, B1}; s_cd[j] = {C0, C1, D0, D1}; s_wp[j] = {wr0, wr1, wi0, wi1}
    __shared__ __align__(16) float s_ab[NWN * 2];
    __shared__ __align__(16) float s_cd[NWN * 2];
    __shared__ __align__(16) float s_wp[NWN * 2];

    const int t  = threadIdx.x;
    const int bc = blockIdx.x >> 3;           // (b*C + c) slice index (8 blocks/slice)
    const int c  = bc & (CN - 1);

    if (t < NWN / 2) {
        const int w0 = 2 * t, w1 = 2 * t + 1;
        const float cf0 = -0.7213475204444817f / sd[w0];   // -log2(e)/(2*sd)
        const float cf1 = -0.7213475204444817f / sd[w1];
        const float mr0 = mur[w0], mi0 = mui[w0];
        const float mr1 = mur[w1], mi1 = mui[w1];
        reinterpret_cast<float4*>(s_ab)[t] =
            make_float4(cf0, cf1, -2.0f * cf0 * mr0, -2.0f * cf1 * mr1);
        reinterpret_cast<float4*>(s_cd)[t] =
            make_float4(-2.0f * cf0 * mi0, -2.0f * cf1 * mi1,
                        cf0 * fmaf(mr0, mr0, mi0 * mi0),
                        cf1 * fmaf(mr1, mr1, mi1 * mi1));
        reinterpret_cast<float4*>(s_wp)[t] =
            make_float4(wr[c * NWN + w0], wr[c * NWN + w1],
                        wi[c * NWN + w0], wi[c * NWN + w1]);
    }
    __syncthreads();

    const int p0   = ((blockIdx.x & 7) << 9) + (t << 1);   // 2 pixels per thread
    const int base = bc * HWN;

    const float2 x_r = *reinterpret_cast<const float2*>(xr + base + p0);
    const float2 x_i = *reinterpret_cast<const float2*>(xi + base + p0);

    // duplicated per-pixel packed values
    const u64t xr0d = pack2(x_r.x, x_r.x);
    const u64t xi0d = pack2(x_i.x, x_i.x);
    const u64t xr1d = pack2(x_r.y, x_r.y);
    const u64t xi1d = pack2(x_i.y, x_i.y);
    const float n0 = fmaf(x_r.x, x_r.x, x_i.x * x_i.x);
    const float n1 = fmaf(x_r.y, x_r.y, x_i.y * x_i.y);
    const u64t n0d = pack2(n0, n0);
    const u64t n1d = pack2(n1, n1);

    u64t accr0 = 0ULL, acci0 = 0ULL;   // {sum even w, sum odd w}
    u64t accr1 = 0ULL, acci1 = 0ULL;

    const ulonglong2* ab2 = reinterpret_cast<const ulonglong2*>(s_ab);
    const ulonglong2* cd2 = reinterpret_cast<const ulonglong2*>(s_cd);
    const ulonglong2* wp2 = reinterpret_cast<const ulonglong2*>(s_wp);

    // ---- depth-2 software pipeline over the 32 weight-pairs ----
    ulonglong2 ab = ab2[0];
    ulonglong2 cd = cd2[0];
    ulonglong2 wp = wp2[0];

#pragma unroll
    for (int j = 0; j < NWN / 2; j++) {
        // prefetch next iteration's coefficients before consuming current ones
        ulonglong2 ab_n, cd_n, wp_n;
        if (j + 1 < NWN / 2) {
            ab_n = ab2[j + 1];
            cd_n = cd2[j + 1];
            wp_n = wp2[j + 1];
        }

        u64t e0 = fma2(ab.x, n0d, cd.y);   // A*n + D
        u64t e1 = fma2(ab.x, n1d, cd.y);
        e0 = fma2(ab.y, xr0d, e0);         // + B*xr
        e1 = fma2(ab.y, xr1d, e1);
        e0 = fma2(cd.x, xi0d, e0);         // + C*xi
        e1 = fma2(cd.x, xi1d, e1);

        const u64t g0 = ex2_2(e0);
        const u64t g1 = ex2_2(e1);

        accr0 = fma2(g0, wp.x, accr0);
        acci0 = fma2(g0, wp.y, acci0);
        accr1 = fma2(g1, wp.x, accr1);
        acci1 = fma2(g1, wp.y, acci1);

        if (j + 1 < NWN / 2) {
            ab = ab_n;
            cd = cd_n;
            wp = wp_n;
        }
    }

    float a, b2;
    const float brc = br[c];
    const float bic = bi[c];

    float4 o;
    unpack2(accr0, a, b2);  o.x = a + b2 + brc;   // pixel p0   real
    unpack2(acci0, a, b2);  o.y = a + b2 + bic;   // pixel p0   imag
    unpack2(accr1, a, b2);  o.z = a + b2 + brc;   // pixel p0+1 real
    unpack2(acci1, a, b2);  o.w = a + b2 + bic;   // pixel p0+1 imag
    *reinterpret_cast<float4*>(out + (size_t)(base + p0) * 2) = o;
}

extern "C" void kernel_launch(void* const* d_in, const int* in_sizes, int n_in,
                              void* d_out, int out_size)
{
    const float* xr  = (const float*)d_in[0];  // x_real  (4,32,64,64)
    const float* xi  = (const float*)d_in[1];  // x_imag
    const float* wr  = (const float*)d_in[2];  // w_real  (32,64)
    const float* wi  = (const float*)d_in[3];  // w_imag
    const float* br  = (const float*)d_in[4];  // b_real  (1,32,1)
    const float* bi  = (const float*)d_in[5];  // b_imag
    const float* mur = (const float*)d_in[6];  // mu_real (64)
    const float* mui = (const float*)d_in[7];  // mu_imag (64)
    const float* sd  = (const float*)d_in[8];  // stddev  (64)
    float* out = (float*)d_out;                // (4,32,64,64,2)

    // 4*32*4096 pixels / (256 threads * 2 pixels) = 1024 blocks
    cplx_rbf_kernel<<<1024, 256>>>(xr, xi, wr, wi, br, bi, mur, mui, sd, out);
}